// round 3
// baseline (speedup 1.0000x reference)
#include <cuda_runtime.h>
#include <math.h>

#define L 8
#define E 8
#define R 64
#define H 2048
#define TOK 8192            // BSZ*SEQ
#define SCALING 0.5f        // R / ALPHA_R

#define TM 128              // token tile
#define KSPLIT 4
#define KCH (H / KSPLIT)    // 512
#define BK 32
#define XS 36               // aproj smem row stride
#define HSS 68              // bproj smem row stride
#define NTILES (TOK / TM + E)   // 72 worst-case tiles

#define FMA2(acc, a, b) asm("fma.rn.f32x2 %0, %1, %2, %0;" : "+l"(acc) : "l"(a), "l"(b))

typedef unsigned long long ull;

// ---------------- scratch --------------------------------------------------
__device__ float g_hpart[KSPLIT][(size_t)TOK * R];
__device__ float g_h[(size_t)TOK * R];
__device__ int   g_gid[TOK];
__device__ float g_coef[TOK];
__device__ int   g_counts[E];
__device__ int   g_cnt[E];
__device__ int   g_off[E];
__device__ int   g_tilestart[E + 1];
__device__ int   g_list[TOK];
__device__ float g_D[L][TOK][E];     // (1-z)-side gate logits source
__device__ float g_D0[TOK][E];       // x-side logits for layer 0
__device__ float g_P[L][E][E][64];   // P[i][g][e][r] = gw_i[e] . Bm[i-1][g][:,r]

__device__ __forceinline__ float sigmoidf_(float v) { return 1.0f / (1.0f + expf(-v)); }

// ---------------- precompute D (hx-side gate logits) ------------------------
// blockIdx.y = source layer s: s==0 -> hs[0] w/ gw0 -> D0;
// s==1 -> hs[1] w/ gw0->D[0] and gw1->D[1]; s>=2 -> hs[s] w/ gw_s -> D[s].
__global__ void __launch_bounds__(256) dgate_kernel(const float* __restrict__ hs,
                                                    const float* __restrict__ gw)
{
    int warp = threadIdx.x >> 5, lane = threadIdx.x & 31;
    int t = blockIdx.x * 8 + warp;
    int s = blockIdx.y;

    const float* src;
    const float* gw0p; const float* gw1p = nullptr;
    float* out0; float* out1 = nullptr;
    if (s == 0)      { src = hs;                      gw0p = gw;             out0 = &g_D0[0][0]; }
    else if (s == 1) { src = hs + (size_t)TOK * H;    gw0p = gw;             out0 = &g_D[0][0][0];
                       gw1p = gw + (size_t)E * H;     out1 = &g_D[1][0][0]; }
    else             { src = hs + (size_t)s * TOK * H; gw0p = gw + (size_t)s * E * H; out0 = &g_D[s][0][0]; }

    const float* xp = src + (size_t)t * H;
    float acc0[E], acc1[E];
#pragma unroll
    for (int e = 0; e < E; e++) { acc0[e] = 0.f; acc1[e] = 0.f; }

#pragma unroll 4
    for (int j = 0; j < H / 128; j++) {
        int k = j * 128 + lane * 4;
        float4 v = *(const float4*)(xp + k);
#pragma unroll
        for (int e = 0; e < E; e++) {
            float4 w = *(const float4*)(gw0p + (size_t)e * H + k);
            acc0[e] += v.x * w.x + v.y * w.y + v.z * w.z + v.w * w.w;
        }
        if (gw1p) {
#pragma unroll
            for (int e = 0; e < E; e++) {
                float4 w = *(const float4*)(gw1p + (size_t)e * H + k);
                acc1[e] += v.x * w.x + v.y * w.y + v.z * w.z + v.w * w.w;
            }
        }
    }
#pragma unroll
    for (int e = 0; e < E; e++) {
#pragma unroll
        for (int o = 16; o > 0; o >>= 1) {
            acc0[e] += __shfl_xor_sync(0xffffffffu, acc0[e], o);
            acc1[e] += __shfl_xor_sync(0xffffffffu, acc1[e], o);
        }
    }
    if (lane < E) {
        out0[t * E + lane] = acc0[lane];
        if (out1) out1[t * E + lane] = acc1[lane];
    }
}

// ---------------- precompute P[i][g][e][r] ----------------------------------
__global__ void __launch_bounds__(256) pmat_kernel(const float* __restrict__ Bm,
                                                   const float* __restrict__ gw)
{
    int g = blockIdx.x, i = blockIdx.y + 1;
    int e = threadIdx.x >> 5, lane = threadIdx.x & 31;

    if (blockIdx.x == 0 && blockIdx.y == 0 && threadIdx.x < E) g_counts[threadIdx.x] = 0;

    const float* Bp  = Bm + ((size_t)(i - 1) * E + g) * H * R;   // [h][r]
    const float* gwp = gw + ((size_t)i * E + e) * H;

    float a0 = 0.f, a1 = 0.f;
    for (int h = 0; h < H; h++) {
        float w = gwp[h];
        a0 = fmaf(w, Bp[h * R + lane], a0);
        a1 = fmaf(w, Bp[h * R + lane + 32], a1);
    }
    float* P = &g_P[i][g][e][0];
    P[lane] = a0;
    P[lane + 32] = a1;
}

// ---------------- per-layer gating (tiny) ------------------------------------
__global__ void __launch_bounds__(256) gate_kernel(const float* __restrict__ gates, int layer)
{
    int warp = threadIdx.x >> 5, lane = threadIdx.x & 31;
    int t = blockIdx.x * 8 + warp;

    float z = sigmoidf_(gates[layer]);
    float omz = 1.0f - z;

    float dotv[E];
    float zc = z;
    if (layer == 0) {
        if (lane < E) dotv[0] = g_D0[t][lane];   // placeholder; handled below
    } else {
        int g = g_gid[t];
        float c = g_coef[t];
        zc = z * c;
        float h0 = g_h[(size_t)t * R + lane];
        float h1 = g_h[(size_t)t * R + lane + 32];
#pragma unroll
        for (int e = 0; e < E; e++) {
            const float* P = &g_P[layer][g][e][0];
            float p = h0 * P[lane] + h1 * P[lane + 32];
#pragma unroll
            for (int o = 16; o > 0; o >>= 1) p += __shfl_xor_sync(0xffffffffu, p, o);
            dotv[e] = p;
        }
    }

    if (lane == 0) {
        float logit[E];
#pragma unroll
        for (int e = 0; e < E; e++) {
            float xs = (layer == 0) ? g_D0[t][e] : dotv[e];
            logit[e] = zc * xs + omz * g_D[layer][t][e];
        }
        float m = logit[0]; int g = 0;
#pragma unroll
        for (int e = 1; e < E; e++) if (logit[e] > m) { m = logit[e]; g = e; }
        float s = 0.f;
#pragma unroll
        for (int e = 0; e < E; e++) s += expf(logit[e] - m);
        g_gid[t]  = g;
        g_coef[t] = SCALING / s;
        atomicAdd(&g_counts[g], 1);
    }
}

// ---------------- fused plan + scatter (single block) ------------------------
__global__ void __launch_bounds__(1024) planscatter_kernel()
{
    __shared__ int scur[E];
    int tid = threadIdx.x;
    if (tid == 0) {
        int off = 0, ts = 0;
        for (int e = 0; e < E; e++) {
            int c = g_counts[e];
            g_cnt[e] = c;
            g_off[e] = off;
            g_tilestart[e] = ts;
            g_counts[e] = 0;      // ready for next layer's gate
            off += c;
            ts += (c + TM - 1) / TM;
        }
        g_tilestart[E] = ts;
    }
    if (tid < E) scur[tid] = 0;
    __syncthreads();

    int lane = tid & 31;
#pragma unroll
    for (int it = 0; it < TOK / 1024; it++) {
        int t = it * 1024 + tid;
        int e = g_gid[t];
        unsigned mask = __match_any_sync(0xffffffffu, e);
        int leader = __ffs(mask) - 1;
        int rank = __popc(mask & ((1u << lane) - 1));
        int base = 0;
        if (lane == leader) base = atomicAdd(&scur[e], __popc(mask));
        base = __shfl_sync(0xffffffffu, base, leader);
        g_list[g_off[e] + base + rank] = t;
    }
}

// ---------------- A projection with inline residual mix ----------------------
__global__ void __launch_bounds__(128) aproj_kernel(const float* __restrict__ A,
                                                    const float* __restrict__ xprev,
                                                    const float* __restrict__ hx,
                                                    const float* __restrict__ gates, int layer)
{
    __shared__ __align__(16) float Xs[TM * XS];
    __shared__ __align__(16) float As[R * XS];
    __shared__ int s_tok[TM];

    int gt = blockIdx.x;
    if (gt >= g_tilestart[E]) return;
    int part = blockIdx.y;
    int e = 0;
    while (gt >= g_tilestart[e + 1]) e++;
    int tile = gt - g_tilestart[e];
    int cnt  = g_cnt[e];
    int base = g_off[e] + tile * TM;

    float z = sigmoidf_(gates[layer]);
    float omz = 1.0f - z;

    int tid = threadIdx.x;
    s_tok[tid] = (tile * TM + tid < cnt) ? g_list[base + tid] : -1;
    __syncthreads();

    int tm = tid >> 3, tn = tid & 7;

    ull acc[8][8];
#pragma unroll
    for (int i = 0; i < 8; i++)
#pragma unroll
        for (int j = 0; j < 8; j++) acc[i][j] = 0ULL;

    int tok = s_tok[tid];
    const float* xprow = (tok >= 0) ? (xprev + (size_t)tok * H + part * KCH) : nullptr;
    const float* hxrow = (tok >= 0) ? (hx    + (size_t)tok * H + part * KCH) : nullptr;
    int ar = tid & 63, ahf = tid >> 6;
    const float* arow = A + (size_t)e * R * H + (size_t)ar * H + part * KCH + ahf * 16;

    const ull* Xs64 = (const ull*)Xs;
    const ull* As64 = (const ull*)As;

    for (int k0 = 0; k0 < KCH; k0 += BK) {
        __syncthreads();
        if (tok >= 0) {
#pragma unroll
            for (int q = 0; q < 8; q++) {
                float4 a = *(const float4*)(xprow + k0 + q * 4);
                float4 b = *(const float4*)(hxrow + k0 + q * 4);
                float4 v;
                v.x = z * a.x + omz * b.x;
                v.y = z * a.y + omz * b.y;
                v.z = z * a.z + omz * b.z;
                v.w = z * a.w + omz * b.w;
                *(float4*)&Xs[tid * XS + q * 4] = v;
            }
        } else {
            float4 zz = make_float4(0, 0, 0, 0);
#pragma unroll
            for (int q = 0; q < 8; q++) *(float4*)&Xs[tid * XS + q * 4] = zz;
        }
#pragma unroll
        for (int q = 0; q < 4; q++)
            *(float4*)&As[ar * XS + ahf * 16 + q * 4] = *(const float4*)(arow + k0 + q * 4);
        __syncthreads();

#pragma unroll 2
        for (int kp = 0; kp < BK / 2; kp++) {
            ull xv[8], bv[8];
#pragma unroll
            for (int i = 0; i < 8; i++) xv[i] = Xs64[(tm + 16 * i) * (XS / 2) + kp];
#pragma unroll
            for (int j = 0; j < 8; j++) bv[j] = As64[(tn + 8 * j) * (XS / 2) + kp];
#pragma unroll
            for (int i = 0; i < 8; i++)
#pragma unroll
                for (int j = 0; j < 8; j++) FMA2(acc[i][j], xv[i], bv[j]);
        }
    }

    float* hp = g_hpart[part];
#pragma unroll
    for (int i = 0; i < 8; i++) {
        int m = tm + 16 * i;
        int t2 = s_tok[m];
        if (t2 >= 0) {
#pragma unroll
            for (int j = 0; j < 8; j++) {
                ull a = acc[i][j];
                float lo = __uint_as_float((unsigned)a);
                float hi = __uint_as_float((unsigned)(a >> 32));
                hp[(size_t)t2 * R + tn + 8 * j] = lo + hi;
            }
        }
    }
}

// ---------------- reduce 4 K-partials (deterministic) -----------------------
__global__ void hreduce_kernel() {
    int i = blockIdx.x * 256 + threadIdx.x;
    const float4* p0 = (const float4*)g_hpart[0];
    const float4* p1 = (const float4*)g_hpart[1];
    const float4* p2 = (const float4*)g_hpart[2];
    const float4* p3 = (const float4*)g_hpart[3];
    float4 a = p0[i], b = p1[i], c = p2[i], d = p3[i];
    float4 o;
    o.x = (a.x + b.x) + (c.x + d.x);
    o.y = (a.y + b.y) + (c.y + d.y);
    o.z = (a.z + b.z) + (c.z + d.z);
    o.w = (a.w + b.w) + (c.w + d.w);
    ((float4*)g_h)[i] = o;
}

// ---------------- B projection ----------------------------------------------
__global__ void __launch_bounds__(128) bproj_kernel(const float* __restrict__ Bm,
                                                    float* __restrict__ y)
{
    extern __shared__ __align__(16) float dsm[];
    float* Hs = dsm;                  // [TM][HSS]
    float* Bs = dsm + TM * HSS;       // [64][HSS]
    __shared__ int s_tok[TM];

    int gt = blockIdx.x;
    if (gt >= g_tilestart[E]) return;
    int e = 0;
    while (gt >= g_tilestart[e + 1]) e++;
    int tile = gt - g_tilestart[e];
    int cnt  = g_cnt[e];
    int base = g_off[e] + tile * TM;
    int h0   = blockIdx.y * 64;

    int tid = threadIdx.x;
    s_tok[tid] = (tile * TM + tid < cnt) ? g_list[base + tid] : -1;
    __syncthreads();

    {
        int tok = s_tok[tid];
        if (tok >= 0) {
            const float4* hr = (const float4*)(g_h + (size_t)tok * R);
#pragma unroll
            for (int q = 0; q < 16; q++) *(float4*)&Hs[tid * HSS + q * 4] = hr[q];
        } else {
            float4 zz = make_float4(0, 0, 0, 0);
#pragma unroll
            for (int q = 0; q < 16; q++) *(float4*)&Hs[tid * HSS + q * 4] = zz;
        }
        int r = tid & 63, hf = tid >> 6;
        const float* br = Bm + ((size_t)e * H + (size_t)(h0 + r)) * R + hf * 32;
#pragma unroll
        for (int q = 0; q < 8; q++)
            *(float4*)&Bs[r * HSS + hf * 32 + q * 4] = *(const float4*)(br + q * 4);
    }
    __syncthreads();

    int tm = tid >> 3, tn = tid & 7;
    const ull* Hs64 = (const ull*)Hs;
    const ull* Bs64 = (const ull*)Bs;

    ull acc[8][8];
#pragma unroll
    for (int i = 0; i < 8; i++)
#pragma unroll
        for (int j = 0; j < 8; j++) acc[i][j] = 0ULL;

#pragma unroll 2
    for (int kp = 0; kp < R / 2; kp++) {
        ull xv[8], bv[8];
#pragma unroll
        for (int i = 0; i < 8; i++) xv[i] = Hs64[(tm + 16 * i) * (HSS / 2) + kp];
#pragma unroll
        for (int j = 0; j < 8; j++) bv[j] = Bs64[(tn + 8 * j) * (HSS / 2) + kp];
#pragma unroll
        for (int i = 0; i < 8; i++)
#pragma unroll
            for (int j = 0; j < 8; j++) FMA2(acc[i][j], xv[i], bv[j]);
    }

#pragma unroll
    for (int i = 0; i < 8; i++) {
        int m = tm + 16 * i;
        int tok = s_tok[m];
        if (tok >= 0) {
            float c = __ldg(&g_coef[tok]);
            float* yr = y + (size_t)tok * H + h0;
#pragma unroll
            for (int j = 0; j < 8; j++) {
                ull a = acc[i][j];
                float lo = __uint_as_float((unsigned)a);
                float hi = __uint_as_float((unsigned)(a >> 32));
                yr[tn + 8 * j] = (lo + hi) * c;
            }
        }
    }
}

// ---------------- launcher --------------------------------------------------
extern "C" void kernel_launch(void* const* d_in, const int* in_sizes, int n_in,
                              void* d_out, int out_size)
{
    const float* hs    = (const float*)d_in[0];  // [L+1, B, S, H]
    const float* gates = (const float*)d_in[1];  // [L]
    const float* A     = (const float*)d_in[2];  // [L, E, R, H]
    const float* Bm    = (const float*)d_in[3];  // [L, E, H, R]
    const float* gw    = (const float*)d_in[4];  // [L, E, H]
    float* y = (float*)d_out;                    // [B, S, H]

    const size_t HS = (size_t)TOK * H;
    const int SMEMB = (TM + 64) * HSS * sizeof(float);

    cudaFuncSetAttribute(bproj_kernel,
                         cudaFuncAttributeMaxDynamicSharedMemorySize, SMEMB);

    // one-time precompute: gate logit sources + P matrices (also zeroes counts)
    pmat_kernel<<<dim3(E, L - 1), 256>>>(Bm, gw);
    dgate_kernel<<<dim3(TOK / 8, L), 256>>>(hs, gw);

    for (int i = 0; i < L; i++) {
        const float* xprev = (i == 0) ? hs : y;
        const float* hx    = hs + (size_t)((i == 0) ? 1 : i) * HS;

        gate_kernel<<<TOK / 8, 256>>>(gates, i);
        planscatter_kernel<<<1, 1024>>>();
        aproj_kernel<<<dim3(NTILES, KSPLIT), 128>>>(A + (size_t)i * E * R * H,
                                                    xprev, hx, gates, i);
        hreduce_kernel<<<TOK * R / 4 / 256, 256>>>();
        bproj_kernel<<<dim3(NTILES, 32), 128, SMEMB>>>(Bm + (size_t)i * E * H * R, y);
    }
}

// round 5
// speedup vs baseline: 1.0200x; 1.0200x over previous
#include <cuda_runtime.h>
#include <math.h>
#include <cstdint>

#define L 8
#define E 8
#define R 64
#define H 2048
#define TOK 8192
#define SCALING 0.5f

#define TM 128
#define KSPLIT 4
#define KCH (H / KSPLIT)     // 512
#define BK 32
#define NC (KCH / BK)        // 16 chunks
#define XS 36                // aproj smem row stride (floats)
#define HSS 68               // bproj smem row stride
#define NTILES (TOK / TM + E)   // 72 worst case

typedef unsigned long long ull;

#define FMA2(acc, a, b) asm("fma.rn.f32x2 %0, %1, %2, %0;" : "+l"(acc) : "l"(a), "l"(b))
#define CP16(d, s)  asm volatile("cp.async.cg.shared.global [%0], [%1], 16;" :: "r"(d), "l"(s))
#define CPCOMMIT()  asm volatile("cp.async.commit_group;" ::: "memory")
#define CPWAIT1()   asm volatile("cp.async.wait_group 1;" ::: "memory")

__device__ __forceinline__ uint32_t smem_u32(const void* p) {
    uint32_t a;
    asm("{.reg .u64 t; cvta.to.shared.u64 t, %1; cvt.u32.u64 %0, t;}" : "=r"(a) : "l"(p));
    return a;
}

// ---------------- scratch ----------------------------------------------------
__device__ float g_xmix[(size_t)TOK * H];
__device__ float g_hpart[KSPLIT][(size_t)TOK * R];
__device__ float g_coef[TOK];
__device__ int   g_counts[E];
__device__ int   g_cnt[E];
__device__ int   g_tilestart[E + 1];
__device__ int   g_list[E * TOK];    // fixed per-expert regions

// ---------------- bookkeeping ------------------------------------------------
__global__ void reset_kernel() {
    if (threadIdx.x < E) g_counts[threadIdx.x] = 0;
}

__global__ void plan_kernel() {
    if (threadIdx.x == 0) {
        int ts = 0;
        for (int e = 0; e < E; e++) {
            int c = g_counts[e];
            g_cnt[e] = c;
            g_tilestart[e] = ts;
            g_counts[e] = 0;            // ready for next layer
            ts += (c + TM - 1) / TM;
        }
        g_tilestart[E] = ts;
    }
}

// ---------------- fused residual-mix + gating + scatter ----------------------
__global__ void __launch_bounds__(256) mix_gate_kernel(
    const float* __restrict__ xprev, const float* __restrict__ hx,
    const float* __restrict__ gw, const float* __restrict__ gates, int layer)
{
    int warp = threadIdx.x >> 5, lane = threadIdx.x & 31;
    int t = blockIdx.x * 8 + warp;

    float z = 1.0f / (1.0f + expf(-gates[layer]));
    float omz = 1.0f - z;

    const float* xp = xprev + (size_t)t * H;
    const float* hp = hx    + (size_t)t * H;
    float*       xm = g_xmix + (size_t)t * H;

    float acc[E];
#pragma unroll
    for (int e = 0; e < E; e++) acc[e] = 0.f;

#pragma unroll 4
    for (int j = 0; j < H / 128; j++) {
        int k = j * 128 + lane * 4;
        float4 a = *(const float4*)(xp + k);
        float4 b = *(const float4*)(hp + k);
        float4 v;
        v.x = z * a.x + omz * b.x;
        v.y = z * a.y + omz * b.y;
        v.z = z * a.z + omz * b.z;
        v.w = z * a.w + omz * b.w;
        *(float4*)(xm + k) = v;
#pragma unroll
        for (int e = 0; e < E; e++) {
            float4 w = *(const float4*)(gw + (size_t)e * H + k);
            acc[e] += v.x * w.x + v.y * w.y + v.z * w.z + v.w * w.w;
        }
    }
#pragma unroll
    for (int e = 0; e < E; e++)
#pragma unroll
        for (int o = 16; o > 0; o >>= 1)
            acc[e] += __shfl_xor_sync(0xffffffffu, acc[e], o);

    if (lane == 0) {
        float m = acc[0]; int g = 0;
#pragma unroll
        for (int e = 1; e < E; e++) if (acc[e] > m) { m = acc[e]; g = e; }
        float s = 0.f;
#pragma unroll
        for (int e = 0; e < E; e++) s += expf(acc[e] - m);
        g_coef[t] = SCALING / s;
        int pos = atomicAdd(&g_counts[g], 1);
        g_list[g * TOK + pos] = t;       // scatter fused (order irrelevant)
    }
}

// ---------------- A projection: cp.async double-buffered FFMA2 GEMM ----------
// Tile 128 tokens x 64 r, K-chunk 512 (KSPLIT=4), BK=32, 2 stages.
__global__ void __launch_bounds__(128) aproj_kernel(const float* __restrict__ A)
{
    extern __shared__ __align__(16) float dsm[];   // 2 stages x (128+64)*36 floats
    __shared__ int s_tok[TM];

    int gt = blockIdx.x;
    if (gt >= g_tilestart[E]) return;
    int part = blockIdx.y;
    int e = 0;
    while (gt >= g_tilestart[e + 1]) e++;
    int tile = gt - g_tilestart[e];
    int cnt  = g_cnt[e];

    int tid = threadIdx.x;
    int idx = tile * TM + tid;
    s_tok[tid] = (idx < cnt) ? g_list[e * TOK + idx] : -1;
    __syncthreads();

    int tok = s_tok[tid];
    int ctok = (tok >= 0) ? tok : s_tok[0];        // clamp: garbage rows masked at store
    const float* xsrc = g_xmix + (size_t)ctok * H + part * KCH;
    int ar = tid & 63, ahf = tid >> 6;
    const float* asrc = A + (size_t)e * R * H + (size_t)ar * H + part * KCH + ahf * 16;

    const int STG_F = (TM + R) * XS;               // floats per stage
    uint32_t sb = smem_u32(dsm);
    uint32_t xdst = sb + tid * XS * 4;
    uint32_t adst = sb + (TM * XS + ar * XS + ahf * 16) * 4;
    const uint32_t STGB = STG_F * 4;

#define STAGE(kb, soff) do {                                         \
        uint32_t xd = xdst + (soff);                                 \
        uint32_t ad = adst + (soff);                                 \
        _Pragma("unroll")                                            \
        for (int q = 0; q < 8; q++) CP16(xd + q * 16, xsrc + (kb) + q * 4); \
        _Pragma("unroll")                                            \
        for (int q = 0; q < 4; q++) CP16(ad + q * 16, asrc + (kb) + q * 4); \
        CPCOMMIT();                                                  \
    } while (0)

    STAGE(0, 0);

    int tm = tid >> 3, tn = tid & 7;
    ull acc[8][8];
#pragma unroll
    for (int i = 0; i < 8; i++)
#pragma unroll
        for (int j = 0; j < 8; j++) acc[i][j] = 0ULL;

    for (int kc = 0; kc < NC; kc++) {
        int nk = (kc + 1 < NC) ? (kc + 1) : (NC - 1);   // clamp: dead prefetch into unused buf
        STAGE(nk * BK, ((kc + 1) & 1) * STGB);
        CPWAIT1();
        __syncthreads();

        const ull* Xs64 = (const ull*)(dsm + (kc & 1) * STG_F);
        const ull* As64 = Xs64 + TM * XS / 2;
#pragma unroll 2
        for (int kp = 0; kp < BK / 2; kp++) {
            ull xv[8], bv[8];
#pragma unroll
            for (int i = 0; i < 8; i++) xv[i] = Xs64[(tm + 16 * i) * (XS / 2) + kp];
#pragma unroll
            for (int j = 0; j < 8; j++) bv[j] = As64[(tn + 8 * j) * (XS / 2) + kp];
#pragma unroll
            for (int i = 0; i < 8; i++)
#pragma unroll
                for (int j = 0; j < 8; j++) FMA2(acc[i][j], xv[i], bv[j]);
        }
        __syncthreads();
    }
#undef STAGE

    float* hp = g_hpart[part];
#pragma unroll
    for (int i = 0; i < 8; i++) {
        int m = tm + 16 * i;
        int t2 = s_tok[m];
        if (t2 >= 0) {
#pragma unroll
            for (int j = 0; j < 8; j++) {
                ull a = acc[i][j];
                float lo = __uint_as_float((unsigned)a);
                float hi = __uint_as_float((unsigned)(a >> 32));
                hp[(size_t)t2 * R + tn + 8 * j] = lo + hi;
            }
        }
    }
}

// ---------------- B projection: fused 4-part reduce + FFMA2 GEMM -------------
// Tile 128 tokens x 64 h-cols, K = R = 64 single pass.
__global__ void __launch_bounds__(128) bproj_kernel(const float* __restrict__ Bm,
                                                    float* __restrict__ y)
{
    extern __shared__ __align__(16) float dsm[];
    float* Hs = dsm;                  // [TM][HSS]
    float* Bs = dsm + TM * HSS;       // [64][HSS]
    __shared__ int s_tok[TM];

    int gt = blockIdx.x;
    if (gt >= g_tilestart[E]) return;
    int e = 0;
    while (gt >= g_tilestart[e + 1]) e++;
    int tile = gt - g_tilestart[e];
    int cnt  = g_cnt[e];
    int h0   = blockIdx.y * 64;

    int tid = threadIdx.x;
    int idx = tile * TM + tid;
    s_tok[tid] = (idx < cnt) ? g_list[e * TOK + idx] : -1;
    __syncthreads();

    {
        int tok = s_tok[tid];
        int ct = (tok >= 0) ? tok : s_tok[0];
        const float4* p0 = (const float4*)(g_hpart[0] + (size_t)ct * R);
        const float4* p1 = (const float4*)(g_hpart[1] + (size_t)ct * R);
        const float4* p2 = (const float4*)(g_hpart[2] + (size_t)ct * R);
        const float4* p3 = (const float4*)(g_hpart[3] + (size_t)ct * R);
#pragma unroll
        for (int q = 0; q < 16; q++) {
            float4 a = p0[q], b = p1[q], c = p2[q], d = p3[q];
            float4 v;
            v.x = (a.x + b.x) + (c.x + d.x);
            v.y = (a.y + b.y) + (c.y + d.y);
            v.z = (a.z + b.z) + (c.z + d.z);
            v.w = (a.w + b.w) + (c.w + d.w);
            *(float4*)&Hs[tid * HSS + q * 4] = v;
        }
        int r = tid & 63, hf = tid >> 6;
        const float* br = Bm + ((size_t)e * H + (size_t)(h0 + r)) * R + hf * 32;
#pragma unroll
        for (int q = 0; q < 8; q++)
            *(float4*)&Bs[r * HSS + hf * 32 + q * 4] = *(const float4*)(br + q * 4);
    }
    __syncthreads();

    int tm = tid >> 3, tn = tid & 7;
    const ull* Hs64 = (const ull*)Hs;
    const ull* Bs64 = (const ull*)Bs;

    ull acc[8][8];
#pragma unroll
    for (int i = 0; i < 8; i++)
#pragma unroll
        for (int j = 0; j < 8; j++) acc[i][j] = 0ULL;

#pragma unroll 2
    for (int kp = 0; kp < R / 2; kp++) {
        ull xv[8], bv[8];
#pragma unroll
        for (int i = 0; i < 8; i++) xv[i] = Hs64[(tm + 16 * i) * (HSS / 2) + kp];
#pragma unroll
        for (int j = 0; j < 8; j++) bv[j] = Bs64[(tn + 8 * j) * (HSS / 2) + kp];
#pragma unroll
        for (int i = 0; i < 8; i++)
#pragma unroll
            for (int j = 0; j < 8; j++) FMA2(acc[i][j], xv[i], bv[j]);
    }

#pragma unroll
    for (int i = 0; i < 8; i++) {
        int m = tm + 16 * i;
        int tok = s_tok[m];
        if (tok >= 0) {
            float c = __ldg(&g_coef[tok]);
            float* yr = y + (size_t)tok * H + h0;
#pragma unroll
            for (int j = 0; j < 8; j++) {
                ull a = acc[i][j];
                float lo = __uint_as_float((unsigned)a);
                float hi = __uint_as_float((unsigned)(a >> 32));
                yr[tn + 8 * j] = (lo + hi) * c;
            }
        }
    }
}

// ---------------- launcher ----------------------------------------------------
extern "C" void kernel_launch(void* const* d_in, const int* in_sizes, int n_in,
                              void* d_out, int out_size)
{
    const float* hs    = (const float*)d_in[0];  // [L+1, B, S, H]
    const float* gates = (const float*)d_in[1];  // [L]
    const float* A     = (const float*)d_in[2];  // [L, E, R, H]
    const float* Bm    = (const float*)d_in[3];  // [L, E, H, R]
    const float* gw    = (const float*)d_in[4];  // [L, E, H]
    float* y = (float*)d_out;

    const size_t HS = (size_t)TOK * H;
    const int ASM = 2 * (TM + R) * XS * 4;       // 55296 B
    const int BSM = (TM + 64) * HSS * 4;         // 52224 B

    cudaFuncSetAttribute(aproj_kernel, cudaFuncAttributeMaxDynamicSharedMemorySize, ASM);
    cudaFuncSetAttribute(bproj_kernel, cudaFuncAttributeMaxDynamicSharedMemorySize, BSM);

    reset_kernel<<<1, 32>>>();
    for (int i = 0; i < L; i++) {
        const float* xprev = (i == 0) ? hs : y;
        const float* hx    = hs + (size_t)((i == 0) ? 1 : i) * HS;

        mix_gate_kernel<<<TOK / 8, 256>>>(xprev, hx, gw + (size_t)i * E * H, gates, i);
        plan_kernel<<<1, 32>>>();
        aproj_kernel<<<dim3(NTILES, KSPLIT), 128, ASM>>>(A + (size_t)i * E * R * H);
        bproj_kernel<<<dim3(NTILES, H / 64), 128, BSM>>>(Bm + (size_t)i * E * H * R, y);
    }
}

// round 6
// speedup vs baseline: 1.1981x; 1.1746x over previous
#include <cuda_runtime.h>
#include <math.h>
#include <cstdint>

#define L 8
#define E 8
#define R 64
#define H 2048
#define TOK 8192
#define SCALING 0.5f

#define TM 128
#define KSPLIT 4
#define KCH (H / KSPLIT)     // 512
#define BK 32
#define NC (KCH / BK)        // 16 chunks
#define XS 36                // aproj smem row stride (floats), 144B = 9 x 16B
#define HSS 68               // bproj smem row stride (floats), 272B = 17 x 16B
#define NTILES (TOK / TM + E)   // 72 worst case

typedef unsigned long long ull;

#define FMA2(acc, a, b) asm("fma.rn.f32x2 %0, %1, %2, %0;" : "+l"(acc) : "l"(a), "l"(b))
#define CP16(d, s)  asm volatile("cp.async.cg.shared.global [%0], [%1], 16;" :: "r"(d), "l"(s))
#define CPCOMMIT()  asm volatile("cp.async.commit_group;" ::: "memory")
#define CPWAIT1()   asm volatile("cp.async.wait_group 1;" ::: "memory")

__device__ __forceinline__ uint32_t smem_u32(const void* p) {
    uint32_t a;
    asm("{.reg .u64 t; cvta.to.shared.u64 t, %1; cvt.u32.u64 %0, t;}" : "=r"(a) : "l"(p));
    return a;
}

// ---------------- scratch ----------------------------------------------------
__device__ float g_xmix[(size_t)TOK * H];
__device__ float g_hpart[KSPLIT][(size_t)TOK * R];
__device__ float g_h[(size_t)TOK * R];
__device__ float g_coef[TOK];
__device__ int   g_counts[E];
__device__ int   g_cnt[E];
__device__ int   g_tilestart[E + 1];
__device__ int   g_list[E * TOK];    // fixed per-expert regions

// ---------------- bookkeeping ------------------------------------------------
__global__ void reset_kernel() {
    if (threadIdx.x < E) g_counts[threadIdx.x] = 0;
}

__global__ void plan_kernel() {
    if (threadIdx.x == 0) {
        int ts = 0;
        for (int e = 0; e < E; e++) {
            int c = g_counts[e];
            g_cnt[e] = c;
            g_tilestart[e] = ts;
            g_counts[e] = 0;            // ready for next layer
            ts += (c + TM - 1) / TM;
        }
        g_tilestart[E] = ts;
    }
}

// ---------------- fused residual-mix + gating + scatter ----------------------
__global__ void __launch_bounds__(256) mix_gate_kernel(
    const float* __restrict__ xprev, const float* __restrict__ hx,
    const float* __restrict__ gw, const float* __restrict__ gates, int layer)
{
    int warp = threadIdx.x >> 5, lane = threadIdx.x & 31;
    int t = blockIdx.x * 8 + warp;

    float z = 1.0f / (1.0f + expf(-gates[layer]));
    float omz = 1.0f - z;

    const float* xp = xprev + (size_t)t * H;
    const float* hp = hx    + (size_t)t * H;
    float*       xm = g_xmix + (size_t)t * H;

    float acc[E];
#pragma unroll
    for (int e = 0; e < E; e++) acc[e] = 0.f;

#pragma unroll 4
    for (int j = 0; j < H / 128; j++) {
        int k = j * 128 + lane * 4;
        float4 a = *(const float4*)(xp + k);
        float4 b = *(const float4*)(hp + k);
        float4 v;
        v.x = z * a.x + omz * b.x;
        v.y = z * a.y + omz * b.y;
        v.z = z * a.z + omz * b.z;
        v.w = z * a.w + omz * b.w;
        *(float4*)(xm + k) = v;
#pragma unroll
        for (int e = 0; e < E; e++) {
            float4 w = *(const float4*)(gw + (size_t)e * H + k);
            acc[e] += v.x * w.x + v.y * w.y + v.z * w.z + v.w * w.w;
        }
    }
#pragma unroll
    for (int e = 0; e < E; e++)
#pragma unroll
        for (int o = 16; o > 0; o >>= 1)
            acc[e] += __shfl_xor_sync(0xffffffffu, acc[e], o);

    if (lane == 0) {
        float m = acc[0]; int g = 0;
#pragma unroll
        for (int e = 1; e < E; e++) if (acc[e] > m) { m = acc[e]; g = e; }
        float s = 0.f;
#pragma unroll
        for (int e = 0; e < E; e++) s += expf(acc[e] - m);
        g_coef[t] = SCALING / s;
        int pos = atomicAdd(&g_counts[g], 1);
        g_list[g * TOK + pos] = t;       // scatter fused (order irrelevant)
    }
}

// ---------------- A projection: cp.async 2-stage + LDS.128 FFMA2 GEMM --------
__global__ void __launch_bounds__(128) aproj_kernel(const float* __restrict__ A)
{
    extern __shared__ __align__(16) float dsm[];   // 2 stages x (128+64)*36 floats
    __shared__ int s_tok[TM];

    int gt = blockIdx.x;
    if (gt >= g_tilestart[E]) return;
    int part = blockIdx.y;
    int e = 0;
    while (gt >= g_tilestart[e + 1]) e++;
    int tile = gt - g_tilestart[e];
    int cnt  = g_cnt[e];

    int tid = threadIdx.x;
    int idx = tile * TM + tid;
    s_tok[tid] = (idx < cnt) ? g_list[e * TOK + idx] : -1;
    __syncthreads();

    int tok = s_tok[tid];
    int ctok = (tok >= 0) ? tok : s_tok[0];        // clamp: garbage rows masked at store
    const float* xsrc = g_xmix + (size_t)ctok * H + part * KCH;
    int ar = tid & 63, ahf = tid >> 6;
    const float* asrc = A + (size_t)e * R * H + (size_t)ar * H + part * KCH + ahf * 16;

    const int STG_F = (TM + R) * XS;               // floats per stage
    uint32_t sb = smem_u32(dsm);
    uint32_t xdst = sb + tid * XS * 4;
    uint32_t adst = sb + (TM * XS + ar * XS + ahf * 16) * 4;
    const uint32_t STGB = STG_F * 4;

#define STAGE(kb, soff) do {                                         \
        uint32_t xd = xdst + (soff);                                 \
        uint32_t ad = adst + (soff);                                 \
        _Pragma("unroll")                                            \
        for (int q = 0; q < 8; q++) CP16(xd + q * 16, xsrc + (kb) + q * 4); \
        _Pragma("unroll")                                            \
        for (int q = 0; q < 4; q++) CP16(ad + q * 16, asrc + (kb) + q * 4); \
        CPCOMMIT();                                                  \
    } while (0)

    STAGE(0, 0);

    int tm = tid >> 3, tn = tid & 7;
    ull acc[8][8];
#pragma unroll
    for (int i = 0; i < 8; i++)
#pragma unroll
        for (int j = 0; j < 8; j++) acc[i][j] = 0ULL;

    for (int kc = 0; kc < NC; kc++) {
        int nk = (kc + 1 < NC) ? (kc + 1) : (NC - 1);   // dead prefetch into unused buf
        STAGE(nk * BK, ((kc + 1) & 1) * STGB);
        CPWAIT1();
        __syncthreads();

        const ulonglong2* X2 = (const ulonglong2*)(dsm + (kc & 1) * STG_F);
        const ulonglong2* A2 = X2 + TM * XS / 4;
#pragma unroll 1
        for (int kq = 0; kq < BK / 4; kq++) {           // 4 k per iter via LDS.128
            ulonglong2 xv[8], bv[8];
#pragma unroll
            for (int i = 0; i < 8; i++) xv[i] = X2[(tm + 16 * i) * (XS / 4) + kq];
#pragma unroll
            for (int j = 0; j < 8; j++) bv[j] = A2[(tn + 8 * j) * (XS / 4) + kq];
#pragma unroll
            for (int i = 0; i < 8; i++)
#pragma unroll
                for (int j = 0; j < 8; j++) FMA2(acc[i][j], xv[i].x, bv[j].x);
#pragma unroll
            for (int i = 0; i < 8; i++)
#pragma unroll
                for (int j = 0; j < 8; j++) FMA2(acc[i][j], xv[i].y, bv[j].y);
        }
        __syncthreads();
    }
#undef STAGE

    float* hp = g_hpart[part];
#pragma unroll
    for (int i = 0; i < 8; i++) {
        int m = tm + 16 * i;
        int t2 = s_tok[m];
        if (t2 >= 0) {
#pragma unroll
            for (int j = 0; j < 8; j++) {
                ull a = acc[i][j];
                float lo = __uint_as_float((unsigned)a);
                float hi = __uint_as_float((unsigned)(a >> 32));
                hp[(size_t)t2 * R + tn + 8 * j] = lo + hi;
            }
        }
    }
}

// ---------------- reduce 4 K-partials (deterministic, tiny) -----------------
__global__ void hreduce_kernel() {
    int i = blockIdx.x * 256 + threadIdx.x;
    const float4* p0 = (const float4*)g_hpart[0];
    const float4* p1 = (const float4*)g_hpart[1];
    const float4* p2 = (const float4*)g_hpart[2];
    const float4* p3 = (const float4*)g_hpart[3];
    float4 a = p0[i], b = p1[i], c = p2[i], d = p3[i];
    float4 o;
    o.x = (a.x + b.x) + (c.x + d.x);
    o.y = (a.y + b.y) + (c.y + d.y);
    o.z = (a.z + b.z) + (c.z + d.z);
    o.w = (a.w + b.w) + (c.w + d.w);
    ((float4*)g_h)[i] = o;
}

// ---------------- B projection: LDS.128 FFMA2 GEMM ---------------------------
__global__ void __launch_bounds__(128) bproj_kernel(const float* __restrict__ Bm,
                                                    float* __restrict__ y)
{
    extern __shared__ __align__(16) float dsm[];
    float* Hs = dsm;                  // [TM][HSS]
    float* Bs = dsm + TM * HSS;       // [64][HSS]
    __shared__ int s_tok[TM];

    int gt = blockIdx.x;
    if (gt >= g_tilestart[E]) return;
    int e = 0;
    while (gt >= g_tilestart[e + 1]) e++;
    int tile = gt - g_tilestart[e];
    int cnt  = g_cnt[e];
    int h0   = blockIdx.y * 64;

    int tid = threadIdx.x;
    int idx = tile * TM + tid;
    s_tok[tid] = (idx < cnt) ? g_list[e * TOK + idx] : -1;
    __syncthreads();

    {
        int tok = s_tok[tid];
        int ct = (tok >= 0) ? tok : s_tok[0];
        const float4* hr = (const float4*)(g_h + (size_t)ct * R);
#pragma unroll
        for (int q = 0; q < 16; q++) *(float4*)&Hs[tid * HSS + q * 4] = hr[q];
        int r = tid & 63, hf = tid >> 6;
        const float* br = Bm + ((size_t)e * H + (size_t)(h0 + r)) * R + hf * 32;
#pragma unroll
        for (int q = 0; q < 8; q++)
            *(float4*)&Bs[r * HSS + hf * 32 + q * 4] = *(const float4*)(br + q * 4);
    }
    __syncthreads();

    int tm = tid >> 3, tn = tid & 7;
    const ulonglong2* H2 = (const ulonglong2*)Hs;
    const ulonglong2* B2 = (const ulonglong2*)Bs;

    ull acc[8][8];
#pragma unroll
    for (int i = 0; i < 8; i++)
#pragma unroll
        for (int j = 0; j < 8; j++) acc[i][j] = 0ULL;

#pragma unroll 1
    for (int kq = 0; kq < R / 4; kq++) {
        ulonglong2 xv[8], bv[8];
#pragma unroll
        for (int i = 0; i < 8; i++) xv[i] = H2[(tm + 16 * i) * (HSS / 4) + kq];
#pragma unroll
        for (int j = 0; j < 8; j++) bv[j] = B2[(tn + 8 * j) * (HSS / 4) + kq];
#pragma unroll
        for (int i = 0; i < 8; i++)
#pragma unroll
            for (int j = 0; j < 8; j++) FMA2(acc[i][j], xv[i].x, bv[j].x);
#pragma unroll
        for (int i = 0; i < 8; i++)
#pragma unroll
            for (int j = 0; j < 8; j++) FMA2(acc[i][j], xv[i].y, bv[j].y);
    }

#pragma unroll
    for (int i = 0; i < 8; i++) {
        int m = tm + 16 * i;
        int tok = s_tok[m];
        if (tok >= 0) {
            float c = __ldg(&g_coef[tok]);
            float* yr = y + (size_t)tok * H + h0;
#pragma unroll
            for (int j = 0; j < 8; j++) {
                ull a = acc[i][j];
                float lo = __uint_as_float((unsigned)a);
                float hi = __uint_as_float((unsigned)(a >> 32));
                yr[tn + 8 * j] = (lo + hi) * c;
            }
        }
    }
}

// ---------------- launcher ----------------------------------------------------
extern "C" void kernel_launch(void* const* d_in, const int* in_sizes, int n_in,
                              void* d_out, int out_size)
{
    const float* hs    = (const float*)d_in[0];  // [L+1, B, S, H]
    const float* gates = (const float*)d_in[1];  // [L]
    const float* A     = (const float*)d_in[2];  // [L, E, R, H]
    const float* Bm    = (const float*)d_in[3];  // [L, E, H, R]
    const float* gw    = (const float*)d_in[4];  // [L, E, H]
    float* y = (float*)d_out;

    const size_t HS = (size_t)TOK * H;
    const int ASM = 2 * (TM + R) * XS * 4;       // 55296 B
    const int BSM = (TM + 64) * HSS * 4;         // 52224 B

    cudaFuncSetAttribute(aproj_kernel, cudaFuncAttributeMaxDynamicSharedMemorySize, ASM);
    cudaFuncSetAttribute(bproj_kernel, cudaFuncAttributeMaxDynamicSharedMemorySize, BSM);

    reset_kernel<<<1, 32>>>();
    for (int i = 0; i < L; i++) {
        const float* xprev = (i == 0) ? hs : y;
        const float* hx    = hs + (size_t)((i == 0) ? 1 : i) * HS;

        mix_gate_kernel<<<TOK / 8, 256>>>(xprev, hx, gw + (size_t)i * E * H, gates, i);
        plan_kernel<<<1, 32>>>();
        aproj_kernel<<<dim3(NTILES, KSPLIT), 128, ASM>>>(A + (size_t)i * E * R * H);
        hreduce_kernel<<<TOK * R / 4 / 256, 256>>>();
        bproj_kernel<<<dim3(NTILES, H / 64), 128, BSM>>>(Bm + (size_t)i * E * H * R, y);
    }
}